// round 13
// baseline (speedup 1.0000x reference)
#include <cuda_runtime.h>
#include <cuda_bf16.h>

// Quantumnet, warp-per-batch-element circuit, statevector (1024 f32) in
// registers as 16 x f32x2 packs per lane. Wire->bit map:
//   lane bits L4..L0  = wires 0,2,4,6,8 ; pack bits P3..P0 = wires 1,3,5,7 ;
//   pack slot (lo/hi) = wire 9.
// Tan-half-angle RYs with globally deferred cosines; deferred slot-swap for
// CNOT(8->9) (R12). R13: each warp processes TWO consecutive elements
// sequentially; grid halves to 512 blocks -> single resident wave (4 CTA/SM
// throughout), prologue amortized 2x, dual-interleaved front GEMM sharing
// weight LDS. Circuit body identical to R12 (regs unchanged).

#define WARPS_PER_BLOCK 8
#define THREADS (WARPS_PER_BLOCK * 32)
typedef unsigned long long u64;

__device__ __forceinline__ u64 pk2(float lo, float hi) {
    u64 r; asm("mov.b64 %0,{%1,%2};" : "=l"(r) : "f"(lo), "f"(hi)); return r;
}
__device__ __forceinline__ void upk2(u64 x, float& lo, float& hi) {
    asm("mov.b64 {%0,%1},%2;" : "=f"(lo), "=f"(hi) : "l"(x));
}
__device__ __forceinline__ u64 fma2(u64 a, u64 b, u64 c) {
    u64 d; asm("fma.rn.f32x2 %0,%1,%2,%3;" : "=l"(d) : "l"(a), "l"(b), "l"(c)); return d;
}
__device__ __forceinline__ u64 mul2(u64 a, u64 b) {
    u64 d; asm("mul.rn.f32x2 %0,%1,%2;" : "=l"(d) : "l"(a), "l"(b)); return d;
}
__device__ __forceinline__ u64 add2(u64 a, u64 b) {
    u64 d; asm("add.rn.f32x2 %0,%1,%2;" : "=l"(d) : "l"(a), "l"(b)); return d;
}
__device__ __forceinline__ u64 shfl64(u64 x, int m) {
    return __shfl_xor_sync(0xffffffffu, x, m);
}
__device__ __forceinline__ float tanh_apx(float x) {
    float y; asm("tanh.approx.f32 %0,%1;" : "=f"(y) : "f"(x)); return y;
}
__device__ __forceinline__ u64 wsum2(u64 x) {
#pragma unroll
    for (int m = 16; m; m >>= 1) x = add2(x, shfl64(x, m));
    return x;
}

// RY on lane bit Q: out = v + t_s * partner
template <int Q>
__device__ __forceinline__ void ry_lane(u64* v, u64 ts) {
#pragma unroll
    for (int r = 0; r < 16; r++) {
        u64 p = shfl64(v[r], 1 << Q);
        v[r] = fma2(ts, p, v[r]);
    }
}

// Fused CNOT(ctrl = pack bit CMASK, tgt = lane bit Q) + RY(tgt wire), tan form
template <int Q, int CMASK>
__device__ __forceinline__ void cnot_ry(u64* v, u64 ts) {
#pragma unroll
    for (int r = 0; r < 16; r++) {
        u64 old = v[r];
        u64 p = shfl64(old, 1 << Q);
        if (r & CMASK) v[r] = fma2(ts, old, p);
        else           v[r] = fma2(ts, p, old);
    }
}

// Fused CNOT(7->8)+RY(w8) when slot parity differs across the mask-1 shuffle:
// consume the partner's 32-bit halves CROSSED (partner has opposite s).
__device__ __forceinline__ void cnot_ry0_cross(u64* v, u64 ts) {
#pragma unroll
    for (int r = 0; r < 16; r++) {
        u64 old = v[r];
        float lo, hi; upk2(old, lo, hi);
        float xl = __shfl_xor_sync(0xffffffffu, lo, 1);
        float xh = __shfl_xor_sync(0xffffffffu, hi, 1);
        u64 p = pk2(xh, xl);   // crossed halves
        if (r & 1) v[r] = fma2(ts, old, p);
        else       v[r] = fma2(ts, p, old);
    }
}

// RY on pack bit PM: X' = X - tY ; Y' = Y + tX
template <int PM>
__device__ __forceinline__ void ry_pack(u64* v, u64 tp, u64 tn) {
#pragma unroll
    for (int r = 0; r < 16; r++) {
        if (!(r & PM)) {
            const int r1 = r | PM;
            u64 X = v[r], Y = v[r1];
            v[r]  = fma2(tn, Y, X);
            v[r1] = fma2(tp, X, Y);
        }
    }
}

// RY on slot bit (wire 9)
__device__ __forceinline__ void ry_slot(u64* v, float t) {
#pragma unroll
    for (int r = 0; r < 16; r++) {
        float lo, hi; upk2(v[r], lo, hi);
        float nlo = fmaf(-t, hi, lo);
        float nhi = fmaf(t, lo, hi);
        v[r] = pk2(nlo, nhi);
    }
}

// CNOT ctrl = lane bit QC, tgt = pack bit PM: predicated pack swaps
template <int QC, int PM>
__device__ __forceinline__ void cnot_lp(u64* v, int lane) {
    const bool ct = (lane >> QC) & 1;
#pragma unroll
    for (int r = 0; r < 16; r++) {
        if (!(r & PM)) {
            const int r1 = r | PM;
            u64 a = v[r], b = v[r1];
            v[r]  = ct ? b : a;
            v[r1] = ct ? a : b;
        }
    }
}

__global__ __launch_bounds__(THREADS, 4)
void qnet_kernel(const float* __restrict__ x,      // [B,512]
                 const float* __restrict__ Wred,   // [10,512]
                 const float* __restrict__ bred,   // [10]
                 const float* __restrict__ qp,     // [150]
                 const float* __restrict__ Wpost,  // [2,10]
                 const float* __restrict__ bpost,  // [2]
                 float* __restrict__ out,          // [B,2]
                 int B) {
    __shared__ u64 sW2[5 * 512];          // packed (Wred[2q], Wred[2q+1])
    __shared__ u64 stab[120];             // [0..59]=(t,t), [60..119]=(-t,-t)
    __shared__ float st1[60];             // scalar t per fixed RY
    __shared__ float scc[60];             // cosines for F product
    __shared__ float sbred[10], sWp[20], sbp[2], sF[1];
    __shared__ float sth[WARPS_PER_BLOCK][20];   // per-warp angles, 2 elements

    const int tid = threadIdx.x;
    for (int i = tid; i < 5 * 512; i += THREADS) {
        int q = i >> 9, col = i & 511;
        sW2[i] = pk2(Wred[(2 * q) * 512 + col], Wred[(2 * q + 1) * 512 + col]);
    }
    if (tid < 60) {
        int k = tid / 10, w = tid % 10;
        float s, c;
        sincosf(qp[(k + 1) * 10 + w] * 0.5f, &s, &c);
        float t = s / c;
        stab[tid] = pk2(t, t); stab[tid + 60] = pk2(-t, -t);
        st1[tid] = t; scc[tid] = c;
    }
    if (tid >= 64 && tid < 74)   sbred[tid - 64] = bred[tid - 64];
    if (tid >= 96 && tid < 116)  sWp[tid - 96] = Wpost[tid - 96];
    if (tid >= 128 && tid < 130) sbp[tid - 128] = bpost[tid - 128];
    __syncthreads();
    if (tid == 0) {
        float f = 1.0f;
#pragma unroll
        for (int i = 0; i < 60; i++) f *= scc[i];
        sF[0] = f;
    }
    __syncthreads();

    const int lane = tid & 31;
    const int warp = tid >> 5;
    const int b0 = (blockIdx.x * WARPS_PER_BLOCK + warp) * 2;
    if (b0 >= B) return;

    // ---- dual front GEMM (two independent acc chains; shared weight LDS) ----
    {
        const float* xr0 = x + (size_t)b0 * 512;
        const float* xr1 = xr0 + 512;
        u64 acca[5], accb[5];
#pragma unroll
        for (int q = 0; q < 5; q++) { acca[q] = 0ull; accb[q] = 0ull; }
#pragma unroll
        for (int j = 0; j < 16; j++) {
            float xva = xr0[lane + 32 * j];
            float xvb = xr1[lane + 32 * j];
            u64 xa2 = pk2(xva, xva), xb2 = pk2(xvb, xvb);
#pragma unroll
            for (int q = 0; q < 5; q++) {
                u64 w = sW2[q * 512 + lane + 32 * j];
                acca[q] = fma2(xa2, w, acca[q]);
                accb[q] = fma2(xb2, w, accb[q]);
            }
        }
#pragma unroll
        for (int q = 0; q < 5; q++) {
            u64 ra = wsum2(acca[q]);
            u64 rb = wsum2(accb[q]);
            if (lane == 0) {
                float p0, p1;
                upk2(ra, p0, p1);
                sth[warp][2 * q]      = tanh_apx(p0 + sbred[2 * q]) * 1.5707963267948966f;
                sth[warp][2 * q + 1]  = tanh_apx(p1 + sbred[2 * q + 1]) * 1.5707963267948966f;
                upk2(rb, p0, p1);
                sth[warp][10 + 2 * q]     = tanh_apx(p0 + sbred[2 * q]) * 1.5707963267948966f;
                sth[warp][10 + 2 * q + 1] = tanh_apx(p1 + sbred[2 * q + 1]) * 1.5707963267948966f;
            }
        }
        __syncwarp();
    }

    // per-lane +-t table offsets (0 -> +t bank, 60 -> -t bank)
    const int o0 = (lane & 16) ? 0 : 60;   // RY w0  (L4)
    const int o2 = (lane & 8)  ? 0 : 60;   // RY w2  (L3)
    const int o4 = (lane & 4)  ? 0 : 60;   // RY w4  (L2)
    const int o6 = (lane & 2)  ? 0 : 60;   // RY w6  (L1)
    const int o8 = (lane & 1)  ? 0 : 60;   // RY w8  (L0)
    const bool L0 = lane & 1;

    // ---- element loop: 2 sequential elements, circuit body = R12 ----
#pragma unroll 1
    for (int e = 0; e < 2; e++) {
        const float* th = &sth[warp][e * 10];

        // product state: H-layer + data RY layer (exact), scaled by F
        float gl[5][2], gp[4][2], g9[2];
#pragma unroll
        for (int q = 0; q < 5; q++) {
            float s, c; __sincosf(th[2 * q] * 0.5f, &s, &c);
            gl[q][0] = (c - s) * 0.7071067811865476f;
            gl[q][1] = (c + s) * 0.7071067811865476f;
        }
#pragma unroll
        for (int q = 0; q < 4; q++) {
            float s, c; __sincosf(th[2 * q + 1] * 0.5f, &s, &c);
            gp[q][0] = (c - s) * 0.7071067811865476f;
            gp[q][1] = (c + s) * 0.7071067811865476f;
        }
        {
            float s, c; __sincosf(th[9] * 0.5f, &s, &c);
            g9[0] = (c - s) * 0.7071067811865476f;
            g9[1] = (c + s) * 0.7071067811865476f;
        }
        float F = sF[0] * ((lane & 16) ? gl[0][1] : gl[0][0]);
        F *= ((lane & 8) ? gl[1][1] : gl[1][0]);
        F *= ((lane & 4) ? gl[2][1] : gl[2][0]);
        F *= ((lane & 2) ? gl[3][1] : gl[3][0]);
        F *= ((lane & 1) ? gl[4][1] : gl[4][0]);
        float hiP[4], loP[4];
#pragma unroll
        for (int i = 0; i < 4; i++) {
            hiP[i] = gp[0][(i >> 1) & 1] * gp[1][i & 1];   // wires 1,3
            loP[i] = gp[2][(i >> 1) & 1] * gp[3][i & 1];   // wires 5,7
        }
        u64 G9F = pk2(F * g9[0], F * g9[1]);
        u64 v[16];
#pragma unroll
        for (int r = 0; r < 16; r++) {
            float m = hiP[r >> 2] * loP[r & 3];
            v[r] = mul2(pk2(m, m), G9F);
        }

        // 6 entangling layers, fully unrolled; slot CNOT (8->9) deferred
#pragma unroll
        for (int k = 0; k < 6; k++) {
            const u64* T = stab + k * 10;
            cnot_lp<4, 8>(v, lane);   // (0->1)
            cnot_lp<3, 4>(v, lane);   // (2->3)
            cnot_lp<2, 2>(v, lane);   // (4->5)
            cnot_lp<1, 1>(v, lane);   // (6->7)
            cnot_ry<3, 8>(v, T[2 + o2]);   // (1->2)+RY w2
            cnot_ry<2, 4>(v, T[4 + o4]);   // (3->4)+RY w4
            cnot_ry<1, 2>(v, T[6 + o6]);   // (5->6)+RY w6
            if (k & 1) {
                cnot_ry<0, 1>(v, T[8 + o8]);      // (7->8)+RY w8, s uniform
            } else {
                cnot_ry0_cross(v, T[8 + o8]);     // opposite s: cross halves
            }
            ry_lane<4>(v, T[0 + o0]);      // RY w0
            ry_pack<8>(v, T[1], T[1 + 60]);
            ry_pack<4>(v, T[3], T[3 + 60]);
            ry_pack<2>(v, T[5], T[5 + 60]);
            ry_pack<1>(v, T[7], T[7 + 60]);
            {
                float t = st1[k * 10 + 9];
                float te = ((k & 1) == 0 && L0) ? -t : t;
                ry_slot(v, te);            // RY w9
            }
        }

        // <Z_w> + output projection, fused
        const u64 P1 = pk2(1.0f, 1.0f), M1 = pk2(-1.0f, -1.0f);
        u64 S2 = 0ull, A8 = 0ull, A4 = 0ull, A2 = 0ull, A1 = 0ull;
#pragma unroll
        for (int r = 0; r < 16; r++) {
            u64 sq = mul2(v[r], v[r]);
            S2 = add2(S2, sq);
            A8 = fma2((r & 8) ? M1 : P1, sq, A8);
            A4 = fma2((r & 4) ? M1 : P1, sq, A4);
            A2 = fma2((r & 2) ? M1 : P1, sq, A2);
            A1 = fma2((r & 1) ? M1 : P1, sq, A1);
        }
        float sl, sh; upk2(S2, sl, sh);
        float Sv = sl + sh;
        float t9 = sl - sh;
        float l8, h8; upk2(A8, l8, h8); float t1 = l8 + h8;
        float l4, h4; upk2(A4, l4, h4); float t3 = l4 + h4;
        float l2, h2; upk2(A2, l2, h2); float t5 = l2 + h2;
        float l1, h1; upk2(A1, l1, h1); float t7 = l1 + h1;
        float t0 = (lane & 16) ? -Sv : Sv;
        float t2 = (lane & 8)  ? -Sv : Sv;
        float t4 = (lane & 4)  ? -Sv : Sv;
        float t6 = (lane & 2)  ? -Sv : Sv;
        float t8 = L0 ? -Sv : Sv;

        float y0 = sWp[0] * t0 + sWp[1] * t1 + sWp[2] * t2 + sWp[3] * t3 + sWp[4] * t4
                 + sWp[5] * t5 + sWp[6] * t6 + sWp[7] * t7 + sWp[8] * t8 + sWp[9] * t9;
        float y1 = sWp[10] * t0 + sWp[11] * t1 + sWp[12] * t2 + sWp[13] * t3 + sWp[14] * t4
                 + sWp[15] * t5 + sWp[16] * t6 + sWp[17] * t7 + sWp[18] * t8 + sWp[19] * t9;
        u64 y2 = wsum2(pk2(y0, y1));
        if (lane == 0) {
            float r0, r1; upk2(y2, r0, r1);
            out[2 * (size_t)(b0 + e) + 0] = r0 + sbp[0];
            out[2 * (size_t)(b0 + e) + 1] = r1 + sbp[1];
        }
    }
}

extern "C" void kernel_launch(void* const* d_in, const int* in_sizes, int n_in,
                              void* d_out, int out_size) {
    const float* x     = (const float*)d_in[0];
    const float* Wred  = (const float*)d_in[1];
    const float* bred  = (const float*)d_in[2];
    const float* qp    = (const float*)d_in[3];
    const float* Wpost = (const float*)d_in[4];
    const float* bpost = (const float*)d_in[5];
    float* out = (float*)d_out;

    int B = in_sizes[0] / 512;
    int elems_per_block = WARPS_PER_BLOCK * 2;
    int blocks = (B + elems_per_block - 1) / elems_per_block;
    qnet_kernel<<<blocks, THREADS>>>(x, Wred, bred, qp, Wpost, bpost, out, B);
}

// round 14
// speedup vs baseline: 1.0332x; 1.0332x over previous
#include <cuda_runtime.h>
#include <cuda_bf16.h>

// Quantumnet split into two kernels:
//  K1: front layer (GEMM + tanh + sincos) -> per-element g-table (20 floats)
//  K2: circuit (R12 body: tan-half-angle RYs, deferred cosines, deferred
//      slot swap), warp-per-element, reads g-table, no weights in smem.
// Wire->bit map in K2: lane bits L4..L0 = wires 0,2,4,6,8 ;
// pack bits P3..P0 = wires 1,3,5,7 ; pack slot (lo/hi) = wire 9.

#define WARPS_PER_BLOCK 8
#define THREADS (WARPS_PER_BLOCK * 32)
#define MAX_B 16384
typedef unsigned long long u64;

__device__ float g_gtab[MAX_B * 20];   // per-element g pairs (scratch)

__device__ __forceinline__ u64 pk2(float lo, float hi) {
    u64 r; asm("mov.b64 %0,{%1,%2};" : "=l"(r) : "f"(lo), "f"(hi)); return r;
}
__device__ __forceinline__ void upk2(u64 x, float& lo, float& hi) {
    asm("mov.b64 {%0,%1},%2;" : "=f"(lo), "=f"(hi) : "l"(x));
}
__device__ __forceinline__ u64 fma2(u64 a, u64 b, u64 c) {
    u64 d; asm("fma.rn.f32x2 %0,%1,%2,%3;" : "=l"(d) : "l"(a), "l"(b), "l"(c)); return d;
}
__device__ __forceinline__ u64 mul2(u64 a, u64 b) {
    u64 d; asm("mul.rn.f32x2 %0,%1,%2;" : "=l"(d) : "l"(a), "l"(b)); return d;
}
__device__ __forceinline__ u64 add2(u64 a, u64 b) {
    u64 d; asm("add.rn.f32x2 %0,%1,%2;" : "=l"(d) : "l"(a), "l"(b)); return d;
}
__device__ __forceinline__ u64 shfl64(u64 x, int m) {
    return __shfl_xor_sync(0xffffffffu, x, m);
}
__device__ __forceinline__ float tanh_apx(float x) {
    float y; asm("tanh.approx.f32 %0,%1;" : "=f"(y) : "f"(x)); return y;
}
__device__ __forceinline__ u64 wsum2(u64 x) {
#pragma unroll
    for (int m = 16; m; m >>= 1) x = add2(x, shfl64(x, m));
    return x;
}

// ============================ Kernel 1: front ============================
// pre = x[b] @ Wred^T + bred; th = tanh(pre)*pi/2;
// g pairs: ((c-s)/sqrt2, (c+s)/sqrt2) per wire, laid out:
//   [0..9]  = gl (wires 0,2,4,6,8), [10..17] = gp (wires 1,3,5,7), [18..19] = g9
__global__ __launch_bounds__(THREADS)
void qnet_front(const float* __restrict__ x, const float* __restrict__ Wred,
                const float* __restrict__ bred, int B) {
    __shared__ u64 sW2[5 * 512];
    __shared__ float sbred[10];
    const int tid = threadIdx.x;
    for (int i = tid; i < 5 * 512; i += THREADS) {
        int q = i >> 9, col = i & 511;
        sW2[i] = pk2(Wred[(2 * q) * 512 + col], Wred[(2 * q + 1) * 512 + col]);
    }
    if (tid < 10) sbred[tid] = bred[tid];
    __syncthreads();

    const int lane = tid & 31;
    const int b = blockIdx.x * WARPS_PER_BLOCK + (tid >> 5);
    if (b >= B) return;

    const float* xr = x + (size_t)b * 512;
    u64 acc2[5];
#pragma unroll
    for (int q = 0; q < 5; q++) acc2[q] = 0ull;
#pragma unroll
    for (int j = 0; j < 16; j++) {
        float xv = xr[lane + 32 * j];
        u64 xv2 = pk2(xv, xv);
#pragma unroll
        for (int q = 0; q < 5; q++)
            acc2[q] = fma2(xv2, sW2[q * 512 + lane + 32 * j], acc2[q]);
    }
    float th[10];
#pragma unroll
    for (int q = 0; q < 5; q++) {
        u64 r2 = wsum2(acc2[q]);
        float p0, p1; upk2(r2, p0, p1);
        th[2 * q]     = tanh_apx(p0 + sbred[2 * q]) * 1.5707963267948966f;
        th[2 * q + 1] = tanh_apx(p1 + sbred[2 * q + 1]) * 1.5707963267948966f;
    }
    // lanes 0..9: one wire each -> write its g pair
    if (lane < 10) {
        int w = lane;
        float s, c; __sincosf(th[w] * 0.5f, &s, &c);
        float lo = (c - s) * 0.7071067811865476f;
        float hi = (c + s) * 0.7071067811865476f;
        int pos;
        if (w == 9)          pos = 18;
        else if (w & 1)      pos = 10 + (w - 1);      // odd w: 10 + 2*((w-1)/2)
        else                 pos = w;                 // even w: 2*(w/2)
        float2* dst = reinterpret_cast<float2*>(&g_gtab[(size_t)b * 20 + pos]);
        *dst = make_float2(lo, hi);
    }
}

// ============================ Kernel 2: circuit ============================

// RY on lane bit Q: out = v + t_s * partner
template <int Q>
__device__ __forceinline__ void ry_lane(u64* v, u64 ts) {
#pragma unroll
    for (int r = 0; r < 16; r++) {
        u64 p = shfl64(v[r], 1 << Q);
        v[r] = fma2(ts, p, v[r]);
    }
}

template <int Q, int CMASK>
__device__ __forceinline__ void cnot_ry(u64* v, u64 ts) {
#pragma unroll
    for (int r = 0; r < 16; r++) {
        u64 old = v[r];
        u64 p = shfl64(old, 1 << Q);
        if (r & CMASK) v[r] = fma2(ts, old, p);
        else           v[r] = fma2(ts, p, old);
    }
}

// Fused CNOT(7->8)+RY(w8) with opposite slot parity across mask-1 shuffle.
__device__ __forceinline__ void cnot_ry0_cross(u64* v, u64 ts) {
#pragma unroll
    for (int r = 0; r < 16; r++) {
        u64 old = v[r];
        float lo, hi; upk2(old, lo, hi);
        float xl = __shfl_xor_sync(0xffffffffu, lo, 1);
        float xh = __shfl_xor_sync(0xffffffffu, hi, 1);
        u64 p = pk2(xh, xl);   // crossed halves
        if (r & 1) v[r] = fma2(ts, old, p);
        else       v[r] = fma2(ts, p, old);
    }
}

template <int PM>
__device__ __forceinline__ void ry_pack(u64* v, u64 tp, u64 tn) {
#pragma unroll
    for (int r = 0; r < 16; r++) {
        if (!(r & PM)) {
            const int r1 = r | PM;
            u64 X = v[r], Y = v[r1];
            v[r]  = fma2(tn, Y, X);
            v[r1] = fma2(tp, X, Y);
        }
    }
}

__device__ __forceinline__ void ry_slot(u64* v, float t) {
#pragma unroll
    for (int r = 0; r < 16; r++) {
        float lo, hi; upk2(v[r], lo, hi);
        float nlo = fmaf(-t, hi, lo);
        float nhi = fmaf(t, lo, hi);
        v[r] = pk2(nlo, nhi);
    }
}

template <int QC, int PM>
__device__ __forceinline__ void cnot_lp(u64* v, int lane) {
    const bool ct = (lane >> QC) & 1;
#pragma unroll
    for (int r = 0; r < 16; r++) {
        if (!(r & PM)) {
            const int r1 = r | PM;
            u64 a = v[r], b = v[r1];
            v[r]  = ct ? b : a;
            v[r1] = ct ? a : b;
        }
    }
}

__global__ __launch_bounds__(THREADS, 4)
void qnet_circuit(const float* __restrict__ qp,     // [150]
                  const float* __restrict__ Wpost,  // [2,10]
                  const float* __restrict__ bpost,  // [2]
                  float* __restrict__ out,          // [B,2]
                  int B) {
    __shared__ u64 stab[120];             // [0..59]=(t,t), [60..119]=(-t,-t)
    __shared__ float st1[60];             // scalar t per fixed RY
    __shared__ float scc[60];             // cosines for F product
    __shared__ float sWp[20], sbp[2], sF[1];

    const int tid = threadIdx.x;
    if (tid < 60) {
        int k = tid / 10, w = tid % 10;
        float s, c;
        sincosf(qp[(k + 1) * 10 + w] * 0.5f, &s, &c);
        float t = s / c;
        stab[tid] = pk2(t, t); stab[tid + 60] = pk2(-t, -t);
        st1[tid] = t; scc[tid] = c;
    }
    if (tid >= 96 && tid < 116)  sWp[tid - 96] = Wpost[tid - 96];
    if (tid >= 128 && tid < 130) sbp[tid - 128] = bpost[tid - 128];
    __syncthreads();
    if (tid == 0) {
        float f = 1.0f;
#pragma unroll
        for (int i = 0; i < 60; i++) f *= scc[i];
        sF[0] = f;
    }
    __syncthreads();

    const int lane = tid & 31;
    const int b = blockIdx.x * WARPS_PER_BLOCK + (tid >> 5);
    if (b >= B) return;

    // ---- load g-table (20 floats, 5 x LDG.128 broadcast) ----
    const float4* gt = reinterpret_cast<const float4*>(&g_gtab[(size_t)b * 20]);
    float4 fa = gt[0];   // gl0lo gl0hi gl1lo gl1hi
    float4 fb = gt[1];   // gl2lo gl2hi gl3lo gl3hi
    float4 fc = gt[2];   // gl4lo gl4hi gp0lo gp0hi
    float4 fd = gt[3];   // gp1lo gp1hi gp2lo gp2hi
    float4 fe = gt[4];   // gp3lo gp3hi g9lo  g9hi

    // ---- product state init, scaled by F (global cosine product) ----
    float F = sF[0] * ((lane & 16) ? fa.y : fa.x);
    F *= ((lane & 8) ? fa.w : fa.z);
    F *= ((lane & 4) ? fb.y : fb.x);
    F *= ((lane & 2) ? fb.w : fb.z);
    F *= ((lane & 1) ? fc.y : fc.x);
    float gp0[2] = {fc.z, fc.w}, gp1[2] = {fd.x, fd.y};
    float gp2[2] = {fd.z, fd.w}, gp3[2] = {fe.x, fe.y};
    float hiP[4], loP[4];
#pragma unroll
    for (int i = 0; i < 4; i++) {
        hiP[i] = gp0[(i >> 1) & 1] * gp1[i & 1];   // wires 1,3
        loP[i] = gp2[(i >> 1) & 1] * gp3[i & 1];   // wires 5,7
    }
    u64 G9F = pk2(F * fe.z, F * fe.w);
    u64 v[16];
#pragma unroll
    for (int r = 0; r < 16; r++) {
        float m = hiP[r >> 2] * loP[r & 3];
        v[r] = mul2(pk2(m, m), G9F);
    }

    // per-lane +-t table offsets (0 -> +t bank, 60 -> -t bank)
    const int o0 = (lane & 16) ? 0 : 60;   // RY w0  (L4)
    const int o2 = (lane & 8)  ? 0 : 60;   // RY w2  (L3)
    const int o4 = (lane & 4)  ? 0 : 60;   // RY w4  (L2)
    const int o6 = (lane & 2)  ? 0 : 60;   // RY w6  (L1)
    const int o8 = (lane & 1)  ? 0 : 60;   // RY w8  (L0)
    const bool L0 = lane & 1;

    // ---- 6 entangling layers, fully unrolled; slot CNOT (8->9) deferred ----
#pragma unroll
    for (int k = 0; k < 6; k++) {
        const u64* T = stab + k * 10;
        cnot_lp<4, 8>(v, lane);   // (0->1)
        cnot_lp<3, 4>(v, lane);   // (2->3)
        cnot_lp<2, 2>(v, lane);   // (4->5)
        cnot_lp<1, 1>(v, lane);   // (6->7)
        cnot_ry<3, 8>(v, T[2 + o2]);   // (1->2)+RY w2
        cnot_ry<2, 4>(v, T[4 + o4]);   // (3->4)+RY w4
        cnot_ry<1, 2>(v, T[6 + o6]);   // (5->6)+RY w6
        if (k & 1) {
            cnot_ry<0, 1>(v, T[8 + o8]);      // (7->8)+RY w8, s uniform
        } else {
            cnot_ry0_cross(v, T[8 + o8]);     // opposite s: cross halves
        }
        ry_lane<4>(v, T[0 + o0]);      // RY w0
        ry_pack<8>(v, T[1], T[1 + 60]);
        ry_pack<4>(v, T[3], T[3 + 60]);
        ry_pack<2>(v, T[5], T[5 + 60]);
        ry_pack<1>(v, T[7], T[7 + 60]);
        {
            float t = st1[k * 10 + 9];
            float te = ((k & 1) == 0 && L0) ? -t : t;
            ry_slot(v, te);            // RY w9
        }
    }

    // ---- <Z_w> + output projection, fused ----
    const u64 P1 = pk2(1.0f, 1.0f), M1 = pk2(-1.0f, -1.0f);
    u64 S2 = 0ull, A8 = 0ull, A4 = 0ull, A2 = 0ull, A1 = 0ull;
#pragma unroll
    for (int r = 0; r < 16; r++) {
        u64 sq = mul2(v[r], v[r]);
        S2 = add2(S2, sq);
        A8 = fma2((r & 8) ? M1 : P1, sq, A8);
        A4 = fma2((r & 4) ? M1 : P1, sq, A4);
        A2 = fma2((r & 2) ? M1 : P1, sq, A2);
        A1 = fma2((r & 1) ? M1 : P1, sq, A1);
    }
    float sl, sh; upk2(S2, sl, sh);
    float Sv = sl + sh;
    float t9 = sl - sh;
    float l8, h8; upk2(A8, l8, h8); float t1 = l8 + h8;
    float l4, h4; upk2(A4, l4, h4); float t3 = l4 + h4;
    float l2, h2; upk2(A2, l2, h2); float t5 = l2 + h2;
    float l1, h1; upk2(A1, l1, h1); float t7 = l1 + h1;
    float t0 = (lane & 16) ? -Sv : Sv;
    float t2 = (lane & 8)  ? -Sv : Sv;
    float t4 = (lane & 4)  ? -Sv : Sv;
    float t6 = (lane & 2)  ? -Sv : Sv;
    float t8 = L0 ? -Sv : Sv;

    float y0 = sWp[0] * t0 + sWp[1] * t1 + sWp[2] * t2 + sWp[3] * t3 + sWp[4] * t4
             + sWp[5] * t5 + sWp[6] * t6 + sWp[7] * t7 + sWp[8] * t8 + sWp[9] * t9;
    float y1 = sWp[10] * t0 + sWp[11] * t1 + sWp[12] * t2 + sWp[13] * t3 + sWp[14] * t4
             + sWp[15] * t5 + sWp[16] * t6 + sWp[17] * t7 + sWp[18] * t8 + sWp[19] * t9;
    u64 y2 = wsum2(pk2(y0, y1));
    if (lane == 0) {
        float r0, r1; upk2(y2, r0, r1);
        out[2 * (size_t)b + 0] = r0 + sbp[0];
        out[2 * (size_t)b + 1] = r1 + sbp[1];
    }
}

extern "C" void kernel_launch(void* const* d_in, const int* in_sizes, int n_in,
                              void* d_out, int out_size) {
    const float* x     = (const float*)d_in[0];
    const float* Wred  = (const float*)d_in[1];
    const float* bred  = (const float*)d_in[2];
    const float* qp    = (const float*)d_in[3];
    const float* Wpost = (const float*)d_in[4];
    const float* bpost = (const float*)d_in[5];
    float* out = (float*)d_out;

    int B = in_sizes[0] / 512;
    int blocks = (B + WARPS_PER_BLOCK - 1) / WARPS_PER_BLOCK;
    qnet_front<<<blocks, THREADS>>>(x, Wred, bred, B);
    qnet_circuit<<<blocks, THREADS>>>(qp, Wpost, bpost, out, B);
}

// round 15
// speedup vs baseline: 1.0487x; 1.0150x over previous
#include <cuda_runtime.h>
#include <cuda_bf16.h>

// Quantumnet split into two kernels:
//  K1 (qnet_front): front layer (GEMM + tanh + sincos) -> per-element g-table.
//      256 blocks; each warp handles 4 consecutive elements as 2 dual-ILP
//      pairs; weight smem fill amortized 4x.
//  K2 (qnet_circuit): circuit (R12 body: tan-half-angle RYs, deferred
//      cosines, deferred slot swap), warp-per-element, reads g-table.
// Wire->bit map in K2: lane bits L4..L0 = wires 0,2,4,6,8 ;
// pack bits P3..P0 = wires 1,3,5,7 ; pack slot (lo/hi) = wire 9.

#define WARPS_PER_BLOCK 8
#define THREADS (WARPS_PER_BLOCK * 32)
#define ELEMS_PER_WARP 4
#define MAX_B 16384
typedef unsigned long long u64;

__device__ float g_gtab[MAX_B * 20];   // per-element g pairs (scratch)

__device__ __forceinline__ u64 pk2(float lo, float hi) {
    u64 r; asm("mov.b64 %0,{%1,%2};" : "=l"(r) : "f"(lo), "f"(hi)); return r;
}
__device__ __forceinline__ void upk2(u64 x, float& lo, float& hi) {
    asm("mov.b64 {%0,%1},%2;" : "=f"(lo), "=f"(hi) : "l"(x));
}
__device__ __forceinline__ u64 fma2(u64 a, u64 b, u64 c) {
    u64 d; asm("fma.rn.f32x2 %0,%1,%2,%3;" : "=l"(d) : "l"(a), "l"(b), "l"(c)); return d;
}
__device__ __forceinline__ u64 mul2(u64 a, u64 b) {
    u64 d; asm("mul.rn.f32x2 %0,%1,%2;" : "=l"(d) : "l"(a), "l"(b)); return d;
}
__device__ __forceinline__ u64 add2(u64 a, u64 b) {
    u64 d; asm("add.rn.f32x2 %0,%1,%2;" : "=l"(d) : "l"(a), "l"(b)); return d;
}
__device__ __forceinline__ u64 shfl64(u64 x, int m) {
    return __shfl_xor_sync(0xffffffffu, x, m);
}
__device__ __forceinline__ float tanh_apx(float x) {
    float y; asm("tanh.approx.f32 %0,%1;" : "=f"(y) : "f"(x)); return y;
}
__device__ __forceinline__ u64 wsum2(u64 x) {
#pragma unroll
    for (int m = 16; m; m >>= 1) x = add2(x, shfl64(x, m));
    return x;
}

// ============================ Kernel 1: front ============================
// pre = x[b] @ Wred^T + bred; th = tanh(pre)*pi/2;
// g pairs ((c-s)/sqrt2, (c+s)/sqrt2) laid out per element:
//   [0..9] = wires 0,2,4,6,8 ; [10..17] = wires 1,3,5,7 ; [18..19] = wire 9.
__global__ __launch_bounds__(THREADS)
void qnet_front(const float* __restrict__ x, const float* __restrict__ Wred,
                const float* __restrict__ bred, int B) {
    __shared__ u64 sW2[5 * 512];
    __shared__ float sbred[10];
    const int tid = threadIdx.x;
    for (int i = tid; i < 5 * 512; i += THREADS) {
        int q = i >> 9, col = i & 511;
        sW2[i] = pk2(Wred[(2 * q) * 512 + col], Wred[(2 * q + 1) * 512 + col]);
    }
    if (tid < 10) sbred[tid] = bred[tid];
    __syncthreads();

    const int lane = tid & 31;
    const int base = (blockIdx.x * WARPS_PER_BLOCK + (tid >> 5)) * ELEMS_PER_WARP;

#pragma unroll 1
    for (int e = 0; e < ELEMS_PER_WARP; e += 2) {
        const int ba = base + e, bb = base + e + 1;
        if (ba >= B) return;
        const bool has_b = (bb < B);
        const float* xra = x + (size_t)ba * 512;
        const float* xrb = has_b ? (xra + 512) : xra;

        u64 acca[5], accb[5];
#pragma unroll
        for (int q = 0; q < 5; q++) { acca[q] = 0ull; accb[q] = 0ull; }
#pragma unroll
        for (int j = 0; j < 16; j++) {
            float xva = xra[lane + 32 * j];
            float xvb = xrb[lane + 32 * j];
            u64 xa2 = pk2(xva, xva), xb2 = pk2(xvb, xvb);
#pragma unroll
            for (int q = 0; q < 5; q++) {
                u64 w = sW2[q * 512 + lane + 32 * j];
                acca[q] = fma2(xa2, w, acca[q]);
                accb[q] = fma2(xb2, w, accb[q]);
            }
        }
        float tha[10], thb[10];
#pragma unroll
        for (int q = 0; q < 5; q++) {
            u64 ra = wsum2(acca[q]);
            u64 rb = wsum2(accb[q]);
            float p0, p1;
            upk2(ra, p0, p1);
            tha[2 * q]     = tanh_apx(p0 + sbred[2 * q]) * 1.5707963267948966f;
            tha[2 * q + 1] = tanh_apx(p1 + sbred[2 * q + 1]) * 1.5707963267948966f;
            upk2(rb, p0, p1);
            thb[2 * q]     = tanh_apx(p0 + sbred[2 * q]) * 1.5707963267948966f;
            thb[2 * q + 1] = tanh_apx(p1 + sbred[2 * q + 1]) * 1.5707963267948966f;
        }
        // lanes 0..9 write element a's pairs; lanes 16..25 write element b's
        int w = -1, bidx = 0;
        float thw = 0.0f;
        if (lane < 10) { w = lane; bidx = ba; thw = tha[w]; }
        else if (has_b && lane >= 16 && lane < 26) { w = lane - 16; bidx = bb; thw = thb[w]; }
        if (w >= 0) {
            float s, c; __sincosf(thw * 0.5f, &s, &c);
            float lo = (c - s) * 0.7071067811865476f;
            float hi = (c + s) * 0.7071067811865476f;
            int pos;
            if (w == 9)     pos = 18;
            else if (w & 1) pos = 10 + (w - 1);
            else            pos = w;
            float2* dst = reinterpret_cast<float2*>(&g_gtab[(size_t)bidx * 20 + pos]);
            *dst = make_float2(lo, hi);
        }
    }
}

// ============================ Kernel 2: circuit ============================

template <int Q>
__device__ __forceinline__ void ry_lane(u64* v, u64 ts) {
#pragma unroll
    for (int r = 0; r < 16; r++) {
        u64 p = shfl64(v[r], 1 << Q);
        v[r] = fma2(ts, p, v[r]);
    }
}

template <int Q, int CMASK>
__device__ __forceinline__ void cnot_ry(u64* v, u64 ts) {
#pragma unroll
    for (int r = 0; r < 16; r++) {
        u64 old = v[r];
        u64 p = shfl64(old, 1 << Q);
        if (r & CMASK) v[r] = fma2(ts, old, p);
        else           v[r] = fma2(ts, p, old);
    }
}

// Fused CNOT(7->8)+RY(w8) with opposite slot parity across mask-1 shuffle.
__device__ __forceinline__ void cnot_ry0_cross(u64* v, u64 ts) {
#pragma unroll
    for (int r = 0; r < 16; r++) {
        u64 old = v[r];
        float lo, hi; upk2(old, lo, hi);
        float xl = __shfl_xor_sync(0xffffffffu, lo, 1);
        float xh = __shfl_xor_sync(0xffffffffu, hi, 1);
        u64 p = pk2(xh, xl);   // crossed halves
        if (r & 1) v[r] = fma2(ts, old, p);
        else       v[r] = fma2(ts, p, old);
    }
}

template <int PM>
__device__ __forceinline__ void ry_pack(u64* v, u64 tp, u64 tn) {
#pragma unroll
    for (int r = 0; r < 16; r++) {
        if (!(r & PM)) {
            const int r1 = r | PM;
            u64 X = v[r], Y = v[r1];
            v[r]  = fma2(tn, Y, X);
            v[r1] = fma2(tp, X, Y);
        }
    }
}

__device__ __forceinline__ void ry_slot(u64* v, float t) {
#pragma unroll
    for (int r = 0; r < 16; r++) {
        float lo, hi; upk2(v[r], lo, hi);
        float nlo = fmaf(-t, hi, lo);
        float nhi = fmaf(t, lo, hi);
        v[r] = pk2(nlo, nhi);
    }
}

template <int QC, int PM>
__device__ __forceinline__ void cnot_lp(u64* v, int lane) {
    const bool ct = (lane >> QC) & 1;
#pragma unroll
    for (int r = 0; r < 16; r++) {
        if (!(r & PM)) {
            const int r1 = r | PM;
            u64 a = v[r], b = v[r1];
            v[r]  = ct ? b : a;
            v[r1] = ct ? a : b;
        }
    }
}

__global__ __launch_bounds__(THREADS, 4)
void qnet_circuit(const float* __restrict__ qp,     // [150]
                  const float* __restrict__ Wpost,  // [2,10]
                  const float* __restrict__ bpost,  // [2]
                  float* __restrict__ out,          // [B,2]
                  int B) {
    __shared__ u64 stab[120];             // [0..59]=(t,t), [60..119]=(-t,-t)
    __shared__ float st1[60];             // scalar t per fixed RY
    __shared__ float scc[60];             // cosines for F product
    __shared__ float sWp[20], sbp[2], sF[1];

    const int tid = threadIdx.x;
    if (tid < 60) {
        int k = tid / 10, w = tid % 10;
        float s, c;
        sincosf(qp[(k + 1) * 10 + w] * 0.5f, &s, &c);
        float t = s / c;
        stab[tid] = pk2(t, t); stab[tid + 60] = pk2(-t, -t);
        st1[tid] = t; scc[tid] = c;
    }
    if (tid >= 96 && tid < 116)  sWp[tid - 96] = Wpost[tid - 96];
    if (tid >= 128 && tid < 130) sbp[tid - 128] = bpost[tid - 128];
    __syncthreads();
    if (tid == 0) {
        float f = 1.0f;
#pragma unroll
        for (int i = 0; i < 60; i++) f *= scc[i];
        sF[0] = f;
    }
    __syncthreads();

    const int lane = tid & 31;
    const int b = blockIdx.x * WARPS_PER_BLOCK + (tid >> 5);
    if (b >= B) return;

    // ---- load g-table (20 floats, 5 x LDG.128 broadcast) ----
    const float4* gt = reinterpret_cast<const float4*>(&g_gtab[(size_t)b * 20]);
    float4 fa = gt[0];   // gl0lo gl0hi gl1lo gl1hi
    float4 fb = gt[1];   // gl2lo gl2hi gl3lo gl3hi
    float4 fc = gt[2];   // gl4lo gl4hi gp0lo gp0hi
    float4 fd = gt[3];   // gp1lo gp1hi gp2lo gp2hi
    float4 fe = gt[4];   // gp3lo gp3hi g9lo  g9hi

    // ---- product state init, scaled by F (global cosine product) ----
    float F = sF[0] * ((lane & 16) ? fa.y : fa.x);
    F *= ((lane & 8) ? fa.w : fa.z);
    F *= ((lane & 4) ? fb.y : fb.x);
    F *= ((lane & 2) ? fb.w : fb.z);
    F *= ((lane & 1) ? fc.y : fc.x);
    float gp0[2] = {fc.z, fc.w}, gp1[2] = {fd.x, fd.y};
    float gp2[2] = {fd.z, fd.w}, gp3[2] = {fe.x, fe.y};
    float hiP[4], loP[4];
#pragma unroll
    for (int i = 0; i < 4; i++) {
        hiP[i] = gp0[(i >> 1) & 1] * gp1[i & 1];   // wires 1,3
        loP[i] = gp2[(i >> 1) & 1] * gp3[i & 1];   // wires 5,7
    }
    u64 G9F = pk2(F * fe.z, F * fe.w);
    u64 v[16];
#pragma unroll
    for (int r = 0; r < 16; r++) {
        float m = hiP[r >> 2] * loP[r & 3];
        v[r] = mul2(pk2(m, m), G9F);
    }

    // per-lane +-t table offsets (0 -> +t bank, 60 -> -t bank)
    const int o0 = (lane & 16) ? 0 : 60;   // RY w0  (L4)
    const int o2 = (lane & 8)  ? 0 : 60;   // RY w2  (L3)
    const int o4 = (lane & 4)  ? 0 : 60;   // RY w4  (L2)
    const int o6 = (lane & 2)  ? 0 : 60;   // RY w6  (L1)
    const int o8 = (lane & 1)  ? 0 : 60;   // RY w8  (L0)
    const bool L0 = lane & 1;

    // ---- 6 entangling layers, fully unrolled; slot CNOT (8->9) deferred ----
#pragma unroll
    for (int k = 0; k < 6; k++) {
        const u64* T = stab + k * 10;
        cnot_lp<4, 8>(v, lane);   // (0->1)
        cnot_lp<3, 4>(v, lane);   // (2->3)
        cnot_lp<2, 2>(v, lane);   // (4->5)
        cnot_lp<1, 1>(v, lane);   // (6->7)
        cnot_ry<3, 8>(v, T[2 + o2]);   // (1->2)+RY w2
        cnot_ry<2, 4>(v, T[4 + o4]);   // (3->4)+RY w4
        cnot_ry<1, 2>(v, T[6 + o6]);   // (5->6)+RY w6
        if (k & 1) {
            cnot_ry<0, 1>(v, T[8 + o8]);      // (7->8)+RY w8, s uniform
        } else {
            cnot_ry0_cross(v, T[8 + o8]);     // opposite s: cross halves
        }
        ry_lane<4>(v, T[0 + o0]);      // RY w0
        ry_pack<8>(v, T[1], T[1 + 60]);
        ry_pack<4>(v, T[3], T[3 + 60]);
        ry_pack<2>(v, T[5], T[5 + 60]);
        ry_pack<1>(v, T[7], T[7 + 60]);
        {
            float t = st1[k * 10 + 9];
            float te = ((k & 1) == 0 && L0) ? -t : t;
            ry_slot(v, te);            // RY w9
        }
    }

    // ---- <Z_w> + output projection, fused ----
    const u64 P1 = pk2(1.0f, 1.0f), M1 = pk2(-1.0f, -1.0f);
    u64 S2 = 0ull, A8 = 0ull, A4 = 0ull, A2 = 0ull, A1 = 0ull;
#pragma unroll
    for (int r = 0; r < 16; r++) {
        u64 sq = mul2(v[r], v[r]);
        S2 = add2(S2, sq);
        A8 = fma2((r & 8) ? M1 : P1, sq, A8);
        A4 = fma2((r & 4) ? M1 : P1, sq, A4);
        A2 = fma2((r & 2) ? M1 : P1, sq, A2);
        A1 = fma2((r & 1) ? M1 : P1, sq, A1);
    }
    float sl, sh; upk2(S2, sl, sh);
    float Sv = sl + sh;
    float t9 = sl - sh;
    float l8, h8; upk2(A8, l8, h8); float t1 = l8 + h8;
    float l4, h4; upk2(A4, l4, h4); float t3 = l4 + h4;
    float l2, h2; upk2(A2, l2, h2); float t5 = l2 + h2;
    float l1, h1; upk2(A1, l1, h1); float t7 = l1 + h1;
    float t0 = (lane & 16) ? -Sv : Sv;
    float t2 = (lane & 8)  ? -Sv : Sv;
    float t4 = (lane & 4)  ? -Sv : Sv;
    float t6 = (lane & 2)  ? -Sv : Sv;
    float t8 = L0 ? -Sv : Sv;

    float y0 = sWp[0] * t0 + sWp[1] * t1 + sWp[2] * t2 + sWp[3] * t3 + sWp[4] * t4
             + sWp[5] * t5 + sWp[6] * t6 + sWp[7] * t7 + sWp[8] * t8 + sWp[9] * t9;
    float y1 = sWp[10] * t0 + sWp[11] * t1 + sWp[12] * t2 + sWp[13] * t3 + sWp[14] * t4
             + sWp[15] * t5 + sWp[16] * t6 + sWp[17] * t7 + sWp[18] * t8 + sWp[19] * t9;
    u64 y2 = wsum2(pk2(y0, y1));
    if (lane == 0) {
        float r0, r1; upk2(y2, r0, r1);
        out[2 * (size_t)b + 0] = r0 + sbp[0];
        out[2 * (size_t)b + 1] = r1 + sbp[1];
    }
}

extern "C" void kernel_launch(void* const* d_in, const int* in_sizes, int n_in,
                              void* d_out, int out_size) {
    const float* x     = (const float*)d_in[0];
    const float* Wred  = (const float*)d_in[1];
    const float* bred  = (const float*)d_in[2];
    const float* qp    = (const float*)d_in[3];
    const float* Wpost = (const float*)d_in[4];
    const float* bpost = (const float*)d_in[5];
    float* out = (float*)d_out;

    int B = in_sizes[0] / 512;
    int front_blocks = (B + WARPS_PER_BLOCK * ELEMS_PER_WARP - 1) /
                       (WARPS_PER_BLOCK * ELEMS_PER_WARP);
    int circ_blocks = (B + WARPS_PER_BLOCK - 1) / WARPS_PER_BLOCK;
    qnet_front<<<front_blocks, THREADS>>>(x, Wred, bred, B);
    qnet_circuit<<<circ_blocks, THREADS>>>(qp, Wpost, bpost, out, B);
}

// round 16
// speedup vs baseline: 1.0873x; 1.0368x over previous
#include <cuda_runtime.h>
#include <cuda_bf16.h>

// Quantumnet fused kernel. Warp-per-batch-element circuit, statevector
// (1024 f32) in registers as 16 x f32x2 packs per lane. Wire->bit map:
//   lane bits L4..L0  = wires 0,2,4,6,8 ; pack bits P3..P0 = wires 1,3,5,7 ;
//   pack slot (lo/hi) = wire 9.
// Tan-half-angle RYs, global cosine product folded into init, deferred slot
// swap for CNOT(8->9) (R12 circuit, bit-exact vs R8).
// R16: FRONT = dual-interleaved GEMM done by warps 0-3 only (2 elements per
// front-warp, sharing every weight LDS -> front weight-LDS halves), angles
// handed to owning warps via smem + one __syncthreads. Circuit unchanged.

#define WARPS_PER_BLOCK 8
#define THREADS (WARPS_PER_BLOCK * 32)
typedef unsigned long long u64;

__device__ __forceinline__ u64 pk2(float lo, float hi) {
    u64 r; asm("mov.b64 %0,{%1,%2};" : "=l"(r) : "f"(lo), "f"(hi)); return r;
}
__device__ __forceinline__ void upk2(u64 x, float& lo, float& hi) {
    asm("mov.b64 {%0,%1},%2;" : "=f"(lo), "=f"(hi) : "l"(x));
}
__device__ __forceinline__ u64 fma2(u64 a, u64 b, u64 c) {
    u64 d; asm("fma.rn.f32x2 %0,%1,%2,%3;" : "=l"(d) : "l"(a), "l"(b), "l"(c)); return d;
}
__device__ __forceinline__ u64 mul2(u64 a, u64 b) {
    u64 d; asm("mul.rn.f32x2 %0,%1,%2;" : "=l"(d) : "l"(a), "l"(b)); return d;
}
__device__ __forceinline__ u64 add2(u64 a, u64 b) {
    u64 d; asm("add.rn.f32x2 %0,%1,%2;" : "=l"(d) : "l"(a), "l"(b)); return d;
}
__device__ __forceinline__ u64 shfl64(u64 x, int m) {
    return __shfl_xor_sync(0xffffffffu, x, m);
}
__device__ __forceinline__ float tanh_apx(float x) {
    float y; asm("tanh.approx.f32 %0,%1;" : "=f"(y) : "f"(x)); return y;
}
__device__ __forceinline__ u64 wsum2(u64 x) {
#pragma unroll
    for (int m = 16; m; m >>= 1) x = add2(x, shfl64(x, m));
    return x;
}

// ---- circuit ops (R12, proven) ----

template <int Q>
__device__ __forceinline__ void ry_lane(u64* v, u64 ts) {
#pragma unroll
    for (int r = 0; r < 16; r++) {
        u64 p = shfl64(v[r], 1 << Q);
        v[r] = fma2(ts, p, v[r]);
    }
}

template <int Q, int CMASK>
__device__ __forceinline__ void cnot_ry(u64* v, u64 ts) {
#pragma unroll
    for (int r = 0; r < 16; r++) {
        u64 old = v[r];
        u64 p = shfl64(old, 1 << Q);
        if (r & CMASK) v[r] = fma2(ts, old, p);
        else           v[r] = fma2(ts, p, old);
    }
}

// Fused CNOT(7->8)+RY(w8) with opposite slot parity across mask-1 shuffle.
__device__ __forceinline__ void cnot_ry0_cross(u64* v, u64 ts) {
#pragma unroll
    for (int r = 0; r < 16; r++) {
        u64 old = v[r];
        float lo, hi; upk2(old, lo, hi);
        float xl = __shfl_xor_sync(0xffffffffu, lo, 1);
        float xh = __shfl_xor_sync(0xffffffffu, hi, 1);
        u64 p = pk2(xh, xl);   // crossed halves
        if (r & 1) v[r] = fma2(ts, old, p);
        else       v[r] = fma2(ts, p, old);
    }
}

template <int PM>
__device__ __forceinline__ void ry_pack(u64* v, u64 tp, u64 tn) {
#pragma unroll
    for (int r = 0; r < 16; r++) {
        if (!(r & PM)) {
            const int r1 = r | PM;
            u64 X = v[r], Y = v[r1];
            v[r]  = fma2(tn, Y, X);
            v[r1] = fma2(tp, X, Y);
        }
    }
}

__device__ __forceinline__ void ry_slot(u64* v, float t) {
#pragma unroll
    for (int r = 0; r < 16; r++) {
        float lo, hi; upk2(v[r], lo, hi);
        float nlo = fmaf(-t, hi, lo);
        float nhi = fmaf(t, lo, hi);
        v[r] = pk2(nlo, nhi);
    }
}

template <int QC, int PM>
__device__ __forceinline__ void cnot_lp(u64* v, int lane) {
    const bool ct = (lane >> QC) & 1;
#pragma unroll
    for (int r = 0; r < 16; r++) {
        if (!(r & PM)) {
            const int r1 = r | PM;
            u64 a = v[r], b = v[r1];
            v[r]  = ct ? b : a;
            v[r1] = ct ? a : b;
        }
    }
}

__global__ __launch_bounds__(THREADS, 4)
void qnet_kernel(const float* __restrict__ x,      // [B,512]
                 const float* __restrict__ Wred,   // [10,512]
                 const float* __restrict__ bred,   // [10]
                 const float* __restrict__ qp,     // [150]
                 const float* __restrict__ Wpost,  // [2,10]
                 const float* __restrict__ bpost,  // [2]
                 float* __restrict__ out,          // [B,2]
                 int B) {
    __shared__ u64 sW2[5 * 512];          // packed (Wred[2q], Wred[2q+1])
    __shared__ u64 stab[120];             // [0..59]=(t,t), [60..119]=(-t,-t)
    __shared__ float st1[60];             // scalar t per fixed RY
    __shared__ float scc[60];             // cosines for F product
    __shared__ float sbred[10], sWp[20], sbp[2], sF[1];
    __shared__ float sth[WARPS_PER_BLOCK][10];   // per-element angles

    const int tid = threadIdx.x;
    for (int i = tid; i < 5 * 512; i += THREADS) {
        int q = i >> 9, col = i & 511;
        sW2[i] = pk2(Wred[(2 * q) * 512 + col], Wred[(2 * q + 1) * 512 + col]);
    }
    if (tid < 60) {
        int k = tid / 10, w = tid % 10;
        float s, c;
        sincosf(qp[(k + 1) * 10 + w] * 0.5f, &s, &c);
        float t = s / c;
        stab[tid] = pk2(t, t); stab[tid + 60] = pk2(-t, -t);
        st1[tid] = t; scc[tid] = c;
    }
    if (tid >= 64 && tid < 74)   sbred[tid - 64] = bred[tid - 64];
    if (tid >= 96 && tid < 116)  sWp[tid - 96] = Wpost[tid - 96];
    if (tid >= 128 && tid < 130) sbp[tid - 128] = bpost[tid - 128];
    __syncthreads();
    if (tid == 0) {
        float f = 1.0f;
#pragma unroll
        for (int i = 0; i < 60; i++) f *= scc[i];
        sF[0] = f;
    }

    const int lane = tid & 31;
    const int warp = tid >> 5;
    const int bbase = blockIdx.x * WARPS_PER_BLOCK;

    // ---- FRONT: warps 0-3 each do a dual-interleaved GEMM for 2 elements
    //      (weight LDS shared across the pair), write angles to sth ----
    if (warp < 4) {
        const int ea = 2 * warp, eb = 2 * warp + 1;
        int ba = bbase + ea; if (ba >= B) ba = B - 1;
        int bb = bbase + eb; if (bb >= B) bb = B - 1;
        const float* xra = x + (size_t)ba * 512;
        const float* xrb = x + (size_t)bb * 512;
        u64 acca[5], accb[5];
#pragma unroll
        for (int q = 0; q < 5; q++) { acca[q] = 0ull; accb[q] = 0ull; }
#pragma unroll
        for (int j = 0; j < 16; j++) {
            float xva = xra[lane + 32 * j];
            float xvb = xrb[lane + 32 * j];
            u64 xa2 = pk2(xva, xva), xb2 = pk2(xvb, xvb);
#pragma unroll
            for (int q = 0; q < 5; q++) {
                u64 w = sW2[q * 512 + lane + 32 * j];
                acca[q] = fma2(xa2, w, acca[q]);
                accb[q] = fma2(xb2, w, accb[q]);
            }
        }
#pragma unroll
        for (int q = 0; q < 5; q++) {
            u64 ra = wsum2(acca[q]);
            u64 rb = wsum2(accb[q]);
            if (lane == 0) {
                float p0, p1;
                upk2(ra, p0, p1);
                sth[ea][2 * q]     = tanh_apx(p0 + sbred[2 * q]) * 1.5707963267948966f;
                sth[ea][2 * q + 1] = tanh_apx(p1 + sbred[2 * q + 1]) * 1.5707963267948966f;
                upk2(rb, p0, p1);
                sth[eb][2 * q]     = tanh_apx(p0 + sbred[2 * q]) * 1.5707963267948966f;
                sth[eb][2 * q + 1] = tanh_apx(p1 + sbred[2 * q + 1]) * 1.5707963267948966f;
            }
        }
    }
    __syncthreads();

    const int b = bbase + warp;
    if (b >= B) return;

    // ---- pick up this warp's angles ----
    float th[10];
#pragma unroll
    for (int i = 0; i < 10; i++) th[i] = sth[warp][i];

    // ---- product state: H-layer + data RY layer (exact), scaled by F ----
    float gl[5][2], gp[4][2], g9[2];
#pragma unroll
    for (int q = 0; q < 5; q++) {
        float s, c; __sincosf(th[2 * q] * 0.5f, &s, &c);
        gl[q][0] = (c - s) * 0.7071067811865476f;
        gl[q][1] = (c + s) * 0.7071067811865476f;
    }
#pragma unroll
    for (int q = 0; q < 4; q++) {
        float s, c; __sincosf(th[2 * q + 1] * 0.5f, &s, &c);
        gp[q][0] = (c - s) * 0.7071067811865476f;
        gp[q][1] = (c + s) * 0.7071067811865476f;
    }
    {
        float s, c; __sincosf(th[9] * 0.5f, &s, &c);
        g9[0] = (c - s) * 0.7071067811865476f;
        g9[1] = (c + s) * 0.7071067811865476f;
    }
    float F = sF[0] * ((lane & 16) ? gl[0][1] : gl[0][0]);
    F *= ((lane & 8) ? gl[1][1] : gl[1][0]);
    F *= ((lane & 4) ? gl[2][1] : gl[2][0]);
    F *= ((lane & 2) ? gl[3][1] : gl[3][0]);
    F *= ((lane & 1) ? gl[4][1] : gl[4][0]);
    float hiP[4], loP[4];
#pragma unroll
    for (int i = 0; i < 4; i++) {
        hiP[i] = gp[0][(i >> 1) & 1] * gp[1][i & 1];   // wires 1,3
        loP[i] = gp[2][(i >> 1) & 1] * gp[3][i & 1];   // wires 5,7
    }
    u64 G9F = pk2(F * g9[0], F * g9[1]);
    u64 v[16];
#pragma unroll
    for (int r = 0; r < 16; r++) {
        float m = hiP[r >> 2] * loP[r & 3];
        v[r] = mul2(pk2(m, m), G9F);
    }

    // per-lane +-t table offsets (0 -> +t bank, 60 -> -t bank)
    const int o0 = (lane & 16) ? 0 : 60;   // RY w0  (L4)
    const int o2 = (lane & 8)  ? 0 : 60;   // RY w2  (L3)
    const int o4 = (lane & 4)  ? 0 : 60;   // RY w4  (L2)
    const int o6 = (lane & 2)  ? 0 : 60;   // RY w6  (L1)
    const int o8 = (lane & 1)  ? 0 : 60;   // RY w8  (L0)
    const bool L0 = lane & 1;

    // ---- 6 entangling layers, fully unrolled; slot CNOT (8->9) deferred ----
#pragma unroll
    for (int k = 0; k < 6; k++) {
        const u64* T = stab + k * 10;
        cnot_lp<4, 8>(v, lane);   // (0->1)
        cnot_lp<3, 4>(v, lane);   // (2->3)
        cnot_lp<2, 2>(v, lane);   // (4->5)
        cnot_lp<1, 1>(v, lane);   // (6->7)
        cnot_ry<3, 8>(v, T[2 + o2]);   // (1->2)+RY w2
        cnot_ry<2, 4>(v, T[4 + o4]);   // (3->4)+RY w4
        cnot_ry<1, 2>(v, T[6 + o6]);   // (5->6)+RY w6
        if (k & 1) {
            cnot_ry<0, 1>(v, T[8 + o8]);      // (7->8)+RY w8, s uniform
        } else {
            cnot_ry0_cross(v, T[8 + o8]);     // opposite s: cross halves
        }
        ry_lane<4>(v, T[0 + o0]);      // RY w0
        ry_pack<8>(v, T[1], T[1 + 60]);
        ry_pack<4>(v, T[3], T[3 + 60]);
        ry_pack<2>(v, T[5], T[5 + 60]);
        ry_pack<1>(v, T[7], T[7 + 60]);
        {
            float t = st1[k * 10 + 9];
            float te = ((k & 1) == 0 && L0) ? -t : t;
            ry_slot(v, te);            // RY w9
        }
    }

    // ---- <Z_w> + output projection, fused ----
    const u64 P1 = pk2(1.0f, 1.0f), M1 = pk2(-1.0f, -1.0f);
    u64 S2 = 0ull, A8 = 0ull, A4 = 0ull, A2 = 0ull, A1 = 0ull;
#pragma unroll
    for (int r = 0; r < 16; r++) {
        u64 sq = mul2(v[r], v[r]);
        S2 = add2(S2, sq);
        A8 = fma2((r & 8) ? M1 : P1, sq, A8);
        A4 = fma2((r & 4) ? M1 : P1, sq, A4);
        A2 = fma2((r & 2) ? M1 : P1, sq, A2);
        A1 = fma2((r & 1) ? M1 : P1, sq, A1);
    }
    float sl, sh; upk2(S2, sl, sh);
    float Sv = sl + sh;
    float t9 = sl - sh;
    float l8, h8; upk2(A8, l8, h8); float t1 = l8 + h8;
    float l4, h4; upk2(A4, l4, h4); float t3 = l4 + h4;
    float l2, h2; upk2(A2, l2, h2); float t5 = l2 + h2;
    float l1, h1; upk2(A1, l1, h1); float t7 = l1 + h1;
    float t0 = (lane & 16) ? -Sv : Sv;
    float t2 = (lane & 8)  ? -Sv : Sv;
    float t4 = (lane & 4)  ? -Sv : Sv;
    float t6 = (lane & 2)  ? -Sv : Sv;
    float t8 = L0 ? -Sv : Sv;

    float y0 = sWp[0] * t0 + sWp[1] * t1 + sWp[2] * t2 + sWp[3] * t3 + sWp[4] * t4
             + sWp[5] * t5 + sWp[6] * t6 + sWp[7] * t7 + sWp[8] * t8 + sWp[9] * t9;
    float y1 = sWp[10] * t0 + sWp[11] * t1 + sWp[12] * t2 + sWp[13] * t3 + sWp[14] * t4
             + sWp[15] * t5 + sWp[16] * t6 + sWp[17] * t7 + sWp[18] * t8 + sWp[19] * t9;
    u64 y2 = wsum2(pk2(y0, y1));
    if (lane == 0) {
        float r0, r1; upk2(y2, r0, r1);
        out[2 * (size_t)b + 0] = r0 + sbp[0];
        out[2 * (size_t)b + 1] = r1 + sbp[1];
    }
}

extern "C" void kernel_launch(void* const* d_in, const int* in_sizes, int n_in,
                              void* d_out, int out_size) {
    const float* x     = (const float*)d_in[0];
    const float* Wred  = (const float*)d_in[1];
    const float* bred  = (const float*)d_in[2];
    const float* qp    = (const float*)d_in[3];
    const float* Wpost = (const float*)d_in[4];
    const float* bpost = (const float*)d_in[5];
    float* out = (float*)d_out;

    int B = in_sizes[0] / 512;
    int blocks = (B + WARPS_PER_BLOCK - 1) / WARPS_PER_BLOCK;
    qnet_kernel<<<blocks, THREADS>>>(x, Wred, bred, qp, Wpost, bpost, out, B);
}